// round 15
// baseline (speedup 1.0000x reference)
#include <cuda_runtime.h>
#include <math.h>

#define B 512
#define V 6890
#define NJ 24
#define D3 (V*3)              /* 20670 */
#define D3PAD 20736           /* 162 * 128 */
#define KF 108
#define OFF_V 0
#define OFF_POSED (B*D3)
#define OFF_SHAPED (2*B*D3)
#define OFF_J (3*B*D3)

typedef unsigned long long ull;
#define FFMA2(acc, a, b) asm("fma.rn.f32x2 %0, %1, %2, %0;" : "+l"(acc) : "l"(a), "l"(b))
__device__ __forceinline__ float2 upk2(ull u) {
    float2 v; asm("mov.b64 {%0, %1}, %2;" : "=f"(v.x), "=f"(v.y) : "l"(u)); return v;
}

// scratch (static device globals; no allocation)
__device__ __align__(16) float g_F[B*KF];
__device__ __align__(16) float g_Dcomb[D3PAD*KF];
__device__ float g_quat[B*NJ*4];
__device__ float g_R[B*NJ*9];
__device__ float g_JsdP[4][NJ][33];   // partial Jr@[shapedirs | v_template]
__device__ float g_Jp[B*72];
__device__ __align__(16) float g_Gskin[B*NJ*12];

// ---------------- pack dirs ----------------
__global__ void k_dirs(const float* __restrict__ shapedirs,
                       const float* __restrict__ posedirs) {
    int idx = blockIdx.x * 256 + threadIdx.x;
    if (idx >= D3PAD * KF) return;
    int row = idx / KF;
    int col = idx - row * KF;
    float v = 0.f;
    if (row < D3) {
        if (col < 10)                    v = shapedirs[row * 10 + col];
        else if (col >= 12 && col < 105) v = posedirs[row * 93 + (col - 12)];
    }
    g_Dcomb[idx] = v;
}

// ---------------- quaternion + rodrigues ----------------
__global__ void k_rot(const float* __restrict__ pose) {
    int i = blockIdx.x * 128 + threadIdx.x;
    if (i >= B * NJ) return;
    float tx = pose[i*3+0], ty = pose[i*3+1], tz = pose[i*3+2];
    float ax = tx + 1e-8f, ay = ty + 1e-8f, az = tz + 1e-8f;
    float angle = sqrtf(ax*ax + ay*ay + az*az);
    float inv = 1.0f / angle;
    float nx = tx*inv, ny = ty*inv, nz = tz*inv;
    float half = 0.5f * angle;
    float c = cosf(half), s = sinf(half);
    float x = s*nx, y = s*ny, z = s*nz, w = c;
    g_quat[i*4+0] = x; g_quat[i*4+1] = y; g_quat[i*4+2] = z; g_quat[i*4+3] = c - 1.0f;
    float xx=x*x, yy=y*y, zz=z*z;
    float wx=w*x, wy=w*y, wz=w*z;
    float xy=x*y, xz=x*z, yz=y*z;
    float* R = &g_R[i*9];
    R[0]=1.f-2.f*(yy+zz); R[1]=2.f*(xy-wz);      R[2]=2.f*(xz+wy);
    R[3]=2.f*(xy+wz);     R[4]=1.f-2.f*(xx+zz);  R[5]=2.f*(yz-wx);
    R[6]=2.f*(xz-wy);     R[7]=2.f*(yz+wx);      R[8]=1.f-2.f*(xx+yy);
}

// ---------------- pack features ----------------
__global__ void k_feat(const float* __restrict__ betas) {
    int idx = blockIdx.x * 256 + threadIdx.x;
    if (idx >= B * KF) return;
    int b = idx / KF;
    int k = idx - b * KF;
    float v = 0.f;
    if (k < 10)                     v = betas[b*10 + k];
    else if (k >= 12 && k < 104)    v = g_quat[b*96 + 4 + (k - 12)];
    else if (k == 104)              v = betas[b*10 + 1];
    g_F[idx] = v;
}

// ---------------- Jsd partials: Jr @ [shapedirs(V,3,10) | v_template(V,3)] ----------------
__global__ void __launch_bounds__(256) k_jsd(const float* __restrict__ Jr,
                                             const float* __restrict__ shapedirs,
                                             const float* __restrict__ v_template) {
    int j = blockIdx.x;
    int part = blockIdx.y;
    int v0 = part * 1723;
    int v1 = min(V, v0 + 1723);

    float acc[33];
    #pragma unroll
    for (int i = 0; i < 33; i++) acc[i] = 0.f;

    for (int v = v0 + threadIdx.x; v < v1; v += 256) {
        float w = __ldg(&Jr[j * V + v]);
        const float* sh = shapedirs + v * 30;
        #pragma unroll
        for (int c = 0; c < 3; c++) {
            #pragma unroll
            for (int k = 0; k < 10; k++)
                acc[c*10 + k] = fmaf(w, __ldg(&sh[c*10 + k]), acc[c*10 + k]);
            acc[30 + c] = fmaf(w, __ldg(&v_template[v*3 + c]), acc[30 + c]);
        }
    }

    __shared__ float red[8][33];
    int lane = threadIdx.x & 31, wid = threadIdx.x >> 5;
    #pragma unroll
    for (int i = 0; i < 33; i++) {
        float s = acc[i];
        s += __shfl_down_sync(0xffffffffu, s, 16);
        s += __shfl_down_sync(0xffffffffu, s, 8);
        s += __shfl_down_sync(0xffffffffu, s, 4);
        s += __shfl_down_sync(0xffffffffu, s, 2);
        s += __shfl_down_sync(0xffffffffu, s, 1);
        if (lane == 0) red[wid][i] = s;
    }
    __syncthreads();
    if (threadIdx.x < 33) {
        float s = 0.f;
        #pragma unroll
        for (int w2 = 0; w2 < 8; w2++) s += red[w2][threadIdx.x];
        g_JsdP[part][j][threadIdx.x] = s;
    }
}

// ---------------- Jp[b,j,:] = Jsd_j @ betas_b + Jt_j ----------------
__global__ void __launch_bounds__(256) k_jp(const float* __restrict__ betas) {
    int t = blockIdx.x * 256 + threadIdx.x;
    int j = t >> 9;
    int b = t & 511;

    float p[33];
    #pragma unroll
    for (int i = 0; i < 33; i++)
        p[i] = g_JsdP[0][j][i] + g_JsdP[1][j][i] + g_JsdP[2][j][i] + g_JsdP[3][j][i];

    float bt[10];
    #pragma unroll
    for (int k = 0; k < 10; k++) bt[k] = betas[b*10 + k];

    #pragma unroll
    for (int c = 0; c < 3; c++) {
        float s = p[30 + c];
        #pragma unroll
        for (int k = 0; k < 10; k++) s = fmaf(p[c*10 + k], bt[k], s);
        g_Jp[b*72 + j*3 + c] = s;
    }
}

// ---------------- v_shaped writer (write-bound, float4 smem reads) ----------------
__global__ void __launch_bounds__(256) k_shaped(const float* __restrict__ shapedirs,
                                                const float* __restrict__ betas,
                                                const float* __restrict__ v_template,
                                                float* __restrict__ out) {
    __shared__ float sb[128 * 12];   // padded rows: 3 float4 each
    int by = blockIdx.y * 128;
    int tid = threadIdx.x;
    for (int i = tid; i < 128 * 10; i += 256) {
        int r = i / 10, k = i - r * 10;
        sb[r * 12 + k] = betas[(by + r) * 10 + k];
    }
    for (int i = tid; i < 128 * 2; i += 256) {
        int r = i >> 1, k = i & 1;
        sb[r * 12 + 10 + k] = 0.f;
    }
    __syncthreads();

    int d = blockIdx.x * 256 + tid;
    if (d >= D3) return;

    float sh[10];
    #pragma unroll
    for (int k = 0; k < 10; k++) sh[k] = __ldg(&shapedirs[d*10 + k]);
    float vt = __ldg(&v_template[d]);

    #pragma unroll 2
    for (int bl = 0; bl < 128; bl++) {
        float4 b0 = *(const float4*)&sb[bl*12 + 0];
        float4 b1 = *(const float4*)&sb[bl*12 + 4];
        float4 b2 = *(const float4*)&sb[bl*12 + 8];
        float acc = vt;
        acc = fmaf(sh[0], b0.x, acc); acc = fmaf(sh[1], b0.y, acc);
        acc = fmaf(sh[2], b0.z, acc); acc = fmaf(sh[3], b0.w, acc);
        acc = fmaf(sh[4], b1.x, acc); acc = fmaf(sh[5], b1.y, acc);
        acc = fmaf(sh[6], b1.z, acc); acc = fmaf(sh[7], b1.w, acc);
        acc = fmaf(sh[8], b2.x, acc); acc = fmaf(sh[9], b2.y, acc);
        out[OFF_SHAPED + (by + bl) * D3 + d] = acc;
    }
}

// ---------------- v_posed GEMM: 128x64 tile, 8x4 micro, FFMA2 via reinterpret ----------------
// Same tile/layout as the 207us baseline; the ONLY change is the inner product:
// LDS.128 results are reinterpreted as packed f32x2 pairs (no mov overhead) and
// accumulated with fma.rn.f32x2, halving FFMA issue count.
__global__ void __launch_bounds__(256) k_gemm(const float* __restrict__ v_template,
                                              float* __restrict__ out) {
    __shared__ float Ds[128 * 36];
    __shared__ float Fs[64 * 36];
    int dtile = blockIdx.x * 128;
    int btile = blockIdx.y * 64;
    int tid = threadIdx.x;
    int tx = tid & 15, ty = tid >> 4;

    ull acc2[8][4];
    #pragma unroll
    for (int i = 0; i < 8; i++)
        #pragma unroll
        for (int j = 0; j < 4; j++) acc2[i][j] = 0ull;   // packed (0.f, 0.f)

    #pragma unroll 1
    for (int kc = 0; kc < 3; kc++) {
        __syncthreads();
        #pragma unroll 1
        for (int i = tid; i < 128 * 9; i += 256) {
            int r = i / 9, q = i - r * 9;
            ((float4*)Ds)[i] = *(const float4*)(g_Dcomb + (dtile + r) * KF + kc*36 + q*4);
        }
        #pragma unroll 1
        for (int i = tid; i < 64 * 9; i += 256) {
            int r = i / 9, q = i - r * 9;
            ((float4*)Fs)[i] = *(const float4*)(g_F + (btile + r) * KF + kc*36 + q*4);
        }
        __syncthreads();

        #pragma unroll
        for (int kq = 0; kq < 9; kq++) {
            ulonglong2 dv[8], fv[4];
            #pragma unroll
            for (int i = 0; i < 8; i++)
                dv[i] = *(const ulonglong2*)&Ds[(tx + i*16) * 36 + kq*4];
            #pragma unroll
            for (int j = 0; j < 4; j++)
                fv[j] = *(const ulonglong2*)&Fs[(ty + j*16) * 36 + kq*4];
            #pragma unroll
            for (int i = 0; i < 8; i++)
                #pragma unroll
                for (int j = 0; j < 4; j++) {
                    FFMA2(acc2[i][j], dv[i].x, fv[j].x);
                    FFMA2(acc2[i][j], dv[i].y, fv[j].y);
                }
        }
    }

    #pragma unroll
    for (int i = 0; i < 8; i++) {
        int d = dtile + tx + i*16;
        if (d >= D3) continue;
        float vt = v_template[d];
        #pragma unroll
        for (int j = 0; j < 4; j++) {
            int b = btile + ty + j*16;
            float2 a = upk2(acc2[i][j]);
            out[OFF_POSED + b * D3 + d] = a.x + a.y + vt;
        }
    }
}

// ---------------- kinematic chain: row-parallel, __ldg reads (207us baseline) ----------------
__global__ void __launch_bounds__(12) k_chain(const float* __restrict__ trans,
                                              float* __restrict__ out) {
    constexpr int PAR[NJ] = {0, 0,0,0, 1,2,3, 4,5,6, 7,8,9, 9,9, 12,13,14, 16,17,18, 19,20,21};

    int tid = threadIdx.x;
    int b = blockIdx.x * 4 + tid / 3;
    int r = tid % 3;
    if (b >= B) return;

    const float* jp = &g_Jp[b * 72];           // [24][3]
    const float* Rb = &g_R[b * NJ * 9];        // [24][9]
    float tr = __ldg(&trans[b * 3 + r]);

    float jpl[NJ*3];
    #pragma unroll
    for (int i = 0; i < NJ*3; i++) jpl[i] = __ldg(&jp[i]);

    float G[NJ][4];

    {
        G[0][0] = __ldg(&Rb[r*3+0]); G[0][1] = __ldg(&Rb[r*3+1]); G[0][2] = __ldg(&Rb[r*3+2]);
        G[0][3] = jpl[r];
        out[OFF_J + b*72 + r] = G[0][3] + tr;
        float px = jpl[0], py = jpl[1], pz = jpl[2];
        float4 gs;
        gs.x = G[0][0]; gs.y = G[0][1]; gs.z = G[0][2];
        gs.w = G[0][3] - (G[0][0]*px + G[0][1]*py + G[0][2]*pz);
        *(float4*)&g_Gskin[(b*NJ + 0)*12 + r*4] = gs;
    }

    #pragma unroll
    for (int i = 1; i < NJ; i++) {
        const int p = PAR[i];
        const float* R = &Rb[i * 9];
        float R0=__ldg(&R[0]),R1=__ldg(&R[1]),R2=__ldg(&R[2]),
              R3=__ldg(&R[3]),R4=__ldg(&R[4]),R5=__ldg(&R[5]),
              R6=__ldg(&R[6]),R7=__ldg(&R[7]),R8=__ldg(&R[8]);
        float px = jpl[i*3+0], py = jpl[i*3+1], pz = jpl[i*3+2];
        float t0 = px - jpl[p*3+0];
        float t1 = py - jpl[p*3+1];
        float t2 = pz - jpl[p*3+2];
        float a0 = G[p][0], a1 = G[p][1], a2 = G[p][2], a3 = G[p][3];
        float g0 = a0*R0 + a1*R3 + a2*R6;
        float g1 = a0*R1 + a1*R4 + a2*R7;
        float g2 = a0*R2 + a1*R5 + a2*R8;
        float g3 = a0*t0 + a1*t1 + a2*t2 + a3;
        G[i][0] = g0; G[i][1] = g1; G[i][2] = g2; G[i][3] = g3;

        out[OFF_J + b*72 + i*3 + r] = g3 + tr;
        float4 gs;
        gs.x = g0; gs.y = g1; gs.z = g2;
        gs.w = g3 - (g0*px + g1*py + g2*pz);
        *(float4*)&g_Gskin[(b*NJ + i)*12 + r*4] = gs;
    }
}

// ---------------- LBS skinning (207us baseline) ----------------
__global__ void __launch_bounds__(256) k_skin(const float* __restrict__ weights,
                                              const float* __restrict__ trans,
                                              float* __restrict__ out) {
    int b = blockIdx.y;
    __shared__ float4 Gs4[NJ * 3];   // 72 float4 = 288 floats
    __shared__ float tr[3];
    int tid = threadIdx.x;
    if (tid < NJ * 3) Gs4[tid] = ((const float4*)(g_Gskin + b * NJ * 12))[tid];
    if (tid < 3) tr[tid] = trans[b*3 + tid];
    __syncthreads();

    int v = blockIdx.x * 256 + tid;
    if (v >= V) return;

    const float* vp = out + OFF_POSED + b * D3 + v * 3;
    float px = vp[0], py = vp[1], pz = vp[2];

    float4 w4[6];
    const float4* wp = (const float4*)(weights + v * NJ);
    #pragma unroll
    for (int q = 0; q < 6; q++) w4[q] = wp[q];
    const float* w = (const float*)w4;

    float T[12];
    #pragma unroll
    for (int r = 0; r < 12; r++) T[r] = 0.f;
    #pragma unroll
    for (int j = 0; j < NJ; j++) {
        float wj = w[j];
        float4 ga = Gs4[j*3+0], gb = Gs4[j*3+1], gc = Gs4[j*3+2];
        T[0] = fmaf(wj, ga.x, T[0]);  T[1] = fmaf(wj, ga.y, T[1]);
        T[2] = fmaf(wj, ga.z, T[2]);  T[3] = fmaf(wj, ga.w, T[3]);
        T[4] = fmaf(wj, gb.x, T[4]);  T[5] = fmaf(wj, gb.y, T[5]);
        T[6] = fmaf(wj, gb.z, T[6]);  T[7] = fmaf(wj, gb.w, T[7]);
        T[8] = fmaf(wj, gc.x, T[8]);  T[9] = fmaf(wj, gc.y, T[9]);
        T[10]= fmaf(wj, gc.z, T[10]); T[11]= fmaf(wj, gc.w, T[11]);
    }

    float ox = T[0]*px + T[1]*py + T[2]*pz  + T[3]  + tr[0];
    float oy = T[4]*px + T[5]*py + T[6]*pz  + T[7]  + tr[1];
    float oz = T[8]*px + T[9]*py + T[10]*pz + T[11] + tr[2];

    float* o = out + OFF_V + b * D3 + v * 3;
    o[0] = ox; o[1] = oy; o[2] = oz;
}

// ---------------- launch (207us baseline order) ----------------
extern "C" void kernel_launch(void* const* d_in, const int* in_sizes, int n_in,
                              void* d_out, int out_size) {
    const float* pose       = (const float*)d_in[0];
    const float* betas      = (const float*)d_in[1];
    const float* trans      = (const float*)d_in[2];
    const float* v_template = (const float*)d_in[3];
    const float* shapedirs  = (const float*)d_in[4];
    const float* posedirs   = (const float*)d_in[5];
    const float* Jr         = (const float*)d_in[6];
    const float* weights    = (const float*)d_in[7];
    float* out = (float*)d_out;

    // joint pipeline (independent of big GEMMs)
    k_rot<<<(B * NJ + 127) / 128, 128>>>(pose);
    dim3 gjsd(NJ, 4);
    k_jsd<<<gjsd, 256>>>(Jr, shapedirs, v_template);
    k_jp<<<48, 256>>>(betas);
    k_chain<<<128, 12>>>(trans, out);

    // blend-shape pipeline
    k_dirs<<<(D3PAD * KF + 255) / 256, 256>>>(shapedirs, posedirs);
    k_feat<<<(B * KF + 255) / 256, 256>>>(betas);

    dim3 gs(81, 4);
    k_shaped<<<gs, 256>>>(shapedirs, betas, v_template, out);

    dim3 g1(162, 8);           // 128-wide d tiles, 64-wide b tiles
    k_gemm<<<g1, 256>>>(v_template, out);

    dim3 g4((V + 255) / 256, B);
    k_skin<<<g4, 256>>>(weights, trans, out);
}

// round 17
// speedup vs baseline: 1.1792x; 1.1792x over previous
#include <cuda_runtime.h>
#include <math.h>

#define B 512
#define V 6890
#define NJ 24
#define D3 (V*3)              /* 20670 */
#define D3PAD 20736           /* 162 * 128 */
#define KF 108
#define OFF_V 0
#define OFF_POSED (B*D3)
#define OFF_SHAPED (2*B*D3)
#define OFF_J (3*B*D3)

// scratch (static device globals; no allocation)
__device__ float g_F[B*KF];
__device__ float g_Dcomb[D3PAD*KF];
__device__ float g_quat[B*NJ*4];
__device__ float g_R[B*NJ*9];
__device__ float g_JsdP[4][NJ][33];   // partial Jr@[shapedirs | v_template]
__device__ float g_Jp[B*72];
__device__ __align__(16) float g_Gskin[B*NJ*12];

// ---------------- pack dirs ----------------
__global__ void k_dirs(const float* __restrict__ shapedirs,
                       const float* __restrict__ posedirs) {
    int idx = blockIdx.x * 256 + threadIdx.x;
    if (idx >= D3PAD * KF) return;
    int row = idx / KF;
    int col = idx - row * KF;
    float v = 0.f;
    if (row < D3) {
        if (col < 10)                    v = shapedirs[row * 10 + col];
        else if (col >= 12 && col < 105) v = posedirs[row * 93 + (col - 12)];
    }
    g_Dcomb[idx] = v;
}

// ---------------- quaternion + rodrigues ----------------
__global__ void k_rot(const float* __restrict__ pose) {
    int i = blockIdx.x * 128 + threadIdx.x;
    if (i >= B * NJ) return;
    float tx = pose[i*3+0], ty = pose[i*3+1], tz = pose[i*3+2];
    float ax = tx + 1e-8f, ay = ty + 1e-8f, az = tz + 1e-8f;
    float angle = sqrtf(ax*ax + ay*ay + az*az);
    float inv = 1.0f / angle;
    float nx = tx*inv, ny = ty*inv, nz = tz*inv;
    float half = 0.5f * angle;
    float c = cosf(half), s = sinf(half);
    float x = s*nx, y = s*ny, z = s*nz, w = c;
    g_quat[i*4+0] = x; g_quat[i*4+1] = y; g_quat[i*4+2] = z; g_quat[i*4+3] = c - 1.0f;
    float xx=x*x, yy=y*y, zz=z*z;
    float wx=w*x, wy=w*y, wz=w*z;
    float xy=x*y, xz=x*z, yz=y*z;
    float* R = &g_R[i*9];
    R[0]=1.f-2.f*(yy+zz); R[1]=2.f*(xy-wz);      R[2]=2.f*(xz+wy);
    R[3]=2.f*(xy+wz);     R[4]=1.f-2.f*(xx+zz);  R[5]=2.f*(yz-wx);
    R[6]=2.f*(xz-wy);     R[7]=2.f*(yz+wx);      R[8]=1.f-2.f*(xx+yy);
}

// ---------------- pack features ----------------
__global__ void k_feat(const float* __restrict__ betas) {
    int idx = blockIdx.x * 256 + threadIdx.x;
    if (idx >= B * KF) return;
    int b = idx / KF;
    int k = idx - b * KF;
    float v = 0.f;
    if (k < 10)                     v = betas[b*10 + k];
    else if (k >= 12 && k < 104)    v = g_quat[b*96 + 4 + (k - 12)];
    else if (k == 104)              v = betas[b*10 + 1];
    g_F[idx] = v;
}

// ---------------- Jsd partials: Jr @ [shapedirs(V,3,10) | v_template(V,3)] ----------------
__global__ void __launch_bounds__(256) k_jsd(const float* __restrict__ Jr,
                                             const float* __restrict__ shapedirs,
                                             const float* __restrict__ v_template) {
    int j = blockIdx.x;
    int part = blockIdx.y;
    int v0 = part * 1723;
    int v1 = min(V, v0 + 1723);

    float acc[33];
    #pragma unroll
    for (int i = 0; i < 33; i++) acc[i] = 0.f;

    for (int v = v0 + threadIdx.x; v < v1; v += 256) {
        float w = __ldg(&Jr[j * V + v]);
        const float* sh = shapedirs + v * 30;
        #pragma unroll
        for (int c = 0; c < 3; c++) {
            #pragma unroll
            for (int k = 0; k < 10; k++)
                acc[c*10 + k] = fmaf(w, __ldg(&sh[c*10 + k]), acc[c*10 + k]);
            acc[30 + c] = fmaf(w, __ldg(&v_template[v*3 + c]), acc[30 + c]);
        }
    }

    __shared__ float red[8][33];
    int lane = threadIdx.x & 31, wid = threadIdx.x >> 5;
    #pragma unroll
    for (int i = 0; i < 33; i++) {
        float s = acc[i];
        s += __shfl_down_sync(0xffffffffu, s, 16);
        s += __shfl_down_sync(0xffffffffu, s, 8);
        s += __shfl_down_sync(0xffffffffu, s, 4);
        s += __shfl_down_sync(0xffffffffu, s, 2);
        s += __shfl_down_sync(0xffffffffu, s, 1);
        if (lane == 0) red[wid][i] = s;
    }
    __syncthreads();
    if (threadIdx.x < 33) {
        float s = 0.f;
        #pragma unroll
        for (int w2 = 0; w2 < 8; w2++) s += red[w2][threadIdx.x];
        g_JsdP[part][j][threadIdx.x] = s;
    }
}

// ---------------- Jp[b,j,:] = Jsd_j @ betas_b + Jt_j ----------------
__global__ void __launch_bounds__(256) k_jp(const float* __restrict__ betas) {
    int t = blockIdx.x * 256 + threadIdx.x;
    int j = t >> 9;
    int b = t & 511;

    float p[33];
    #pragma unroll
    for (int i = 0; i < 33; i++)
        p[i] = g_JsdP[0][j][i] + g_JsdP[1][j][i] + g_JsdP[2][j][i] + g_JsdP[3][j][i];

    float bt[10];
    #pragma unroll
    for (int k = 0; k < 10; k++) bt[k] = betas[b*10 + k];

    #pragma unroll
    for (int c = 0; c < 3; c++) {
        float s = p[30 + c];
        #pragma unroll
        for (int k = 0; k < 10; k++) s = fmaf(p[c*10 + k], bt[k], s);
        g_Jp[b*72 + j*3 + c] = s;
    }
}

// ---------------- v_posed + v_shaped fused GEMM: 128x64 tile, 8x4 micro ----------------
// v_shaped = accumulator snapshot after K columns 0..11 of chunk 0
// (cols 0-9 = shapedirs x betas, cols 10,11 zero-padded) + v_template.
__global__ void __launch_bounds__(256, 2) k_gemm(const float* __restrict__ v_template,
                                                 float* __restrict__ out) {
    __shared__ float Ds[128 * 36];
    __shared__ float Fs[64 * 36];
    int dtile = blockIdx.x * 128;
    int btile = blockIdx.y * 64;
    int tid = threadIdx.x;
    int tx = tid & 15, ty = tid >> 4;

    float acc[8][4];
    #pragma unroll
    for (int i = 0; i < 8; i++)
        #pragma unroll
        for (int j = 0; j < 4; j++) acc[i][j] = 0.f;

    #pragma unroll 1
    for (int kc = 0; kc < 3; kc++) {
        __syncthreads();
        #pragma unroll 1
        for (int i = tid; i < 128 * 9; i += 256) {
            int r = i / 9, q = i - r * 9;
            ((float4*)Ds)[i] = *(const float4*)(g_Dcomb + (dtile + r) * KF + kc*36 + q*4);
        }
        #pragma unroll 1
        for (int i = tid; i < 64 * 9; i += 256) {
            int r = i / 9, q = i - r * 9;
            ((float4*)Fs)[i] = *(const float4*)(g_F + (btile + r) * KF + kc*36 + q*4);
        }
        __syncthreads();

        #pragma unroll
        for (int kq = 0; kq < 9; kq++) {
            float4 dv[8], fv[4];
            #pragma unroll
            for (int i = 0; i < 8; i++)
                dv[i] = *(const float4*)&Ds[(tx + i*16) * 36 + kq*4];
            #pragma unroll
            for (int j = 0; j < 4; j++)
                fv[j] = *(const float4*)&Fs[(ty + j*16) * 36 + kq*4];
            #pragma unroll
            for (int i = 0; i < 8; i++)
                #pragma unroll
                for (int j = 0; j < 4; j++) {
                    float a = acc[i][j];
                    a = fmaf(dv[i].x, fv[j].x, a);
                    a = fmaf(dv[i].y, fv[j].y, a);
                    a = fmaf(dv[i].z, fv[j].z, a);
                    a = fmaf(dv[i].w, fv[j].w, a);
                    acc[i][j] = a;
                }

            // v_shaped snapshot: after chunk 0, kq==2 (K columns 0..11 done)
            if (kq == 2 && kc == 0) {
                #pragma unroll
                for (int i = 0; i < 8; i++) {
                    int d = dtile + tx + i*16;
                    if (d >= D3) continue;
                    float vt = __ldg(&v_template[d]);
                    #pragma unroll
                    for (int j = 0; j < 4; j++) {
                        int b = btile + ty + j*16;
                        out[OFF_SHAPED + b * D3 + d] = acc[i][j] + vt;
                    }
                }
            }
        }
    }

    #pragma unroll
    for (int i = 0; i < 8; i++) {
        int d = dtile + tx + i*16;
        if (d >= D3) continue;
        float vt = __ldg(&v_template[d]);
        #pragma unroll
        for (int j = 0; j < 4; j++) {
            int b = btile + ty + j*16;
            out[OFF_POSED + b * D3 + d] = acc[i][j] + vt;
        }
    }
}

// ---------------- kinematic chain: row-parallel, __ldg reads ----------------
__global__ void __launch_bounds__(12) k_chain(const float* __restrict__ trans,
                                              float* __restrict__ out) {
    constexpr int PAR[NJ] = {0, 0,0,0, 1,2,3, 4,5,6, 7,8,9, 9,9, 12,13,14, 16,17,18, 19,20,21};

    int tid = threadIdx.x;
    int b = blockIdx.x * 4 + tid / 3;
    int r = tid % 3;
    if (b >= B) return;

    const float* jp = &g_Jp[b * 72];
    const float* Rb = &g_R[b * NJ * 9];
    float tr = __ldg(&trans[b * 3 + r]);

    float jpl[NJ*3];
    #pragma unroll
    for (int i = 0; i < NJ*3; i++) jpl[i] = __ldg(&jp[i]);

    float G[NJ][4];

    {
        G[0][0] = __ldg(&Rb[r*3+0]); G[0][1] = __ldg(&Rb[r*3+1]); G[0][2] = __ldg(&Rb[r*3+2]);
        G[0][3] = jpl[r];
        out[OFF_J + b*72 + r] = G[0][3] + tr;
        float px = jpl[0], py = jpl[1], pz = jpl[2];
        float4 gs;
        gs.x = G[0][0]; gs.y = G[0][1]; gs.z = G[0][2];
        gs.w = G[0][3] - (G[0][0]*px + G[0][1]*py + G[0][2]*pz);
        *(float4*)&g_Gskin[(b*NJ + 0)*12 + r*4] = gs;
    }

    #pragma unroll
    for (int i = 1; i < NJ; i++) {
        const int p = PAR[i];
        const float* R = &Rb[i * 9];
        float R0=__ldg(&R[0]),R1=__ldg(&R[1]),R2=__ldg(&R[2]),
              R3=__ldg(&R[3]),R4=__ldg(&R[4]),R5=__ldg(&R[5]),
              R6=__ldg(&R[6]),R7=__ldg(&R[7]),R8=__ldg(&R[8]);
        float px = jpl[i*3+0], py = jpl[i*3+1], pz = jpl[i*3+2];
        float t0 = px - jpl[p*3+0];
        float t1 = py - jpl[p*3+1];
        float t2 = pz - jpl[p*3+2];
        float a0 = G[p][0], a1 = G[p][1], a2 = G[p][2], a3 = G[p][3];
        float g0 = a0*R0 + a1*R3 + a2*R6;
        float g1 = a0*R1 + a1*R4 + a2*R7;
        float g2 = a0*R2 + a1*R5 + a2*R8;
        float g3 = a0*t0 + a1*t1 + a2*t2 + a3;
        G[i][0] = g0; G[i][1] = g1; G[i][2] = g2; G[i][3] = g3;

        out[OFF_J + b*72 + i*3 + r] = g3 + tr;
        float4 gs;
        gs.x = g0; gs.y = g1; gs.z = g2;
        gs.w = g3 - (g0*px + g1*py + g2*pz);
        *(float4*)&g_Gskin[(b*NJ + i)*12 + r*4] = gs;
    }
}

// ---------------- LBS skinning ----------------
__global__ void __launch_bounds__(256) k_skin(const float* __restrict__ weights,
                                              const float* __restrict__ trans,
                                              float* __restrict__ out) {
    int b = blockIdx.y;
    __shared__ float4 Gs4[NJ * 3];
    __shared__ float tr[3];
    int tid = threadIdx.x;
    if (tid < NJ * 3) Gs4[tid] = ((const float4*)(g_Gskin + b * NJ * 12))[tid];
    if (tid < 3) tr[tid] = trans[b*3 + tid];
    __syncthreads();

    int v = blockIdx.x * 256 + tid;
    if (v >= V) return;

    const float* vp = out + OFF_POSED + b * D3 + v * 3;
    float px = vp[0], py = vp[1], pz = vp[2];

    float4 w4[6];
    const float4* wp = (const float4*)(weights + v * NJ);
    #pragma unroll
    for (int q = 0; q < 6; q++) w4[q] = wp[q];
    const float* w = (const float*)w4;

    float T[12];
    #pragma unroll
    for (int r = 0; r < 12; r++) T[r] = 0.f;
    #pragma unroll
    for (int j = 0; j < NJ; j++) {
        float wj = w[j];
        float4 ga = Gs4[j*3+0], gb = Gs4[j*3+1], gc = Gs4[j*3+2];
        T[0] = fmaf(wj, ga.x, T[0]);  T[1] = fmaf(wj, ga.y, T[1]);
        T[2] = fmaf(wj, ga.z, T[2]);  T[3] = fmaf(wj, ga.w, T[3]);
        T[4] = fmaf(wj, gb.x, T[4]);  T[5] = fmaf(wj, gb.y, T[5]);
        T[6] = fmaf(wj, gb.z, T[6]);  T[7] = fmaf(wj, gb.w, T[7]);
        T[8] = fmaf(wj, gc.x, T[8]);  T[9] = fmaf(wj, gc.y, T[9]);
        T[10]= fmaf(wj, gc.z, T[10]); T[11]= fmaf(wj, gc.w, T[11]);
    }

    float ox = T[0]*px + T[1]*py + T[2]*pz  + T[3]  + tr[0];
    float oy = T[4]*px + T[5]*py + T[6]*pz  + T[7]  + tr[1];
    float oz = T[8]*px + T[9]*py + T[10]*pz + T[11] + tr[2];

    float* o = out + OFF_V + b * D3 + v * 3;
    o[0] = ox; o[1] = oy; o[2] = oz;
}

// ---------------- launch ----------------
extern "C" void kernel_launch(void* const* d_in, const int* in_sizes, int n_in,
                              void* d_out, int out_size) {
    const float* pose       = (const float*)d_in[0];
    const float* betas      = (const float*)d_in[1];
    const float* trans      = (const float*)d_in[2];
    const float* v_template = (const float*)d_in[3];
    const float* shapedirs  = (const float*)d_in[4];
    const float* posedirs   = (const float*)d_in[5];
    const float* Jr         = (const float*)d_in[6];
    const float* weights    = (const float*)d_in[7];
    float* out = (float*)d_out;

    // joint pipeline (independent of big GEMM)
    k_rot<<<(B * NJ + 127) / 128, 128>>>(pose);
    dim3 gjsd(NJ, 4);
    k_jsd<<<gjsd, 256>>>(Jr, shapedirs, v_template);
    k_jp<<<48, 256>>>(betas);
    k_chain<<<128, 12>>>(trans, out);

    // blend-shape pipeline (k_gemm now also writes v_shaped)
    k_dirs<<<(D3PAD * KF + 255) / 256, 256>>>(shapedirs, posedirs);
    k_feat<<<(B * KF + 255) / 256, 256>>>(betas);

    dim3 g1(162, 8);           // 128-wide d tiles, 64-wide b tiles
    k_gemm<<<g1, 256>>>(v_template, out);

    dim3 g4((V + 255) / 256, B);
    k_skin<<<g4, 256>>>(weights, trans, out);
}